// round 11
// baseline (speedup 1.0000x reference)
#include <cuda_runtime.h>
#include <cuda_fp16.h>
#include <math.h>
#include <stdint.h>

#define NNODE  100000
#define EMAX   3200000
#define EPAD   4000064              // E + 8*N headroom (padded CSR)
#define HDIM   128
#define CDIM   10
#define NGRAPH 512

// ---------------- scratch (device globals; no allocation allowed) -------
__device__ __half g_hs16 [(NNODE + 1) * HDIM]; // +1 dummy zero row
__device__ __half g_feat16[NNODE * HDIM];
__device__ uint2  g_bfrag[3 * 8 * 16 * 32];    // W in mma B-fragment layout
__device__ float g_h10 [(NNODE + 1) * CDIM];   // +1 dummy zero row
__device__ int   g_deg [NNODE];
__device__ float g_dinv[NNODE];
__device__ int   g_rowptr[NNODE + 1];
__device__ int   g_cursor[NNODE];
__device__ int   g_col [EPAD];
__device__ int   g_bsum[128];
__device__ int   g_boff[128];
__device__ float g_sums[NGRAPH * CDIM];
__device__ float g_cnts[NGRAPH];

__device__ __forceinline__ int clampi(int v, int n) {
    return (v < 0) ? 0 : ((v >= n) ? n - 1 : v);
}

// ---------------- init: zero everything + pre-fill g_col with dummy -----
__global__ void k_zero(int n) {
    int i = blockIdx.x * blockDim.x + threadIdx.x;
    if (i < EPAD) g_col[i] = NNODE;         // dummy src (zero row)
    if (i < n) g_deg[i] = 0;
    if (i < NGRAPH * CDIM) g_sums[i] = 0.0f;
    if (i < NGRAPH) g_cnts[i] = 0.0f;
    if (i < HDIM / 2) ((unsigned int*)(g_hs16 + NNODE * HDIM))[i] = 0u;
    if (i < CDIM) g_h10[NNODE * CDIM + i] = 0.0f;
}

__global__ void k_count(const int* __restrict__ ei,
                        const int* __restrict__ batch, int E, int n) {
    int e = blockIdx.x * blockDim.x + threadIdx.x;
    if (e < E) atomicAdd(&g_deg[clampi(ei[E + e], n)], 1);
    if (e < n) atomicAdd(&g_cnts[clampi(batch[e], NGRAPH)], 1.0f);
}

// fused: dinv + W fragment packing
__global__ void k_dinv_prepW(const float* __restrict__ W0,
                             const float* __restrict__ W1,
                             const float* __restrict__ W2, int n) {
    int idx = blockIdx.x * blockDim.x + threadIdx.x;
    if (idx < n) g_dinv[idx] = rsqrtf((float)(g_deg[idx] + 1));
    if (idx < 3 * 8 * 16 * 32) {
        int lane = idx & 31;
        int f = (idx >> 5) & 15;
        int s = (idx >> 9) & 7;
        int l = idx >> 12;
        const float* W = (l == 0) ? W0 : (l == 1) ? W1 : W2;
        int kb = s * 16 + 2 * (lane & 3);
        int nn = f * 8 + (lane >> 2);
        __half2 h0 = __floats2half2_rn(W[kb * HDIM + nn], W[(kb + 1) * HDIM + nn]);
        __half2 h1 = __floats2half2_rn(W[(kb + 8) * HDIM + nn], W[(kb + 9) * HDIM + nn]);
        uint2 v;
        v.x = *(unsigned int*)&h0;
        v.y = *(unsigned int*)&h1;
        g_bfrag[idx] = v;
    }
}

// scans operate on PADDED degrees: pdeg = (deg+7) & ~7
__global__ void k_scan1(int n) {
    __shared__ int s[1024];
    int t = threadIdx.x;
    int i = blockIdx.x * 1024 + t;
    s[t] = (i < n) ? ((g_deg[i] + 7) & ~7) : 0;
    __syncthreads();
    for (int st = 512; st > 0; st >>= 1) {
        if (t < st) s[t] += s[t + st];
        __syncthreads();
    }
    if (t == 0) g_bsum[blockIdx.x] = s[0];
}

__global__ void k_scan2(int nb) {
    __shared__ int s[128];
    int t = threadIdx.x;
    int my = (t < nb) ? g_bsum[t] : 0;
    s[t] = my;
    __syncthreads();
    for (int st = 1; st < 128; st <<= 1) {
        int v = (t >= st) ? s[t - st] : 0;
        __syncthreads();
        s[t] += v;
        __syncthreads();
    }
    g_boff[t] = s[t] - my;
}

__global__ void k_scan3(int n) {
    __shared__ int s[1024];
    int t = threadIdx.x;
    int i = blockIdx.x * 1024 + t;
    int v0 = (i < n) ? ((g_deg[i] + 7) & ~7) : 0;
    s[t] = v0;
    __syncthreads();
    for (int st = 1; st < 1024; st <<= 1) {
        int v = (t >= st) ? s[t - st] : 0;
        __syncthreads();
        s[t] += v;
        __syncthreads();
    }
    if (i < n) {
        int excl = g_boff[blockIdx.x] + s[t] - v0;
        g_rowptr[i] = excl;
        g_cursor[i] = excl;
        if (i == n - 1) g_rowptr[n] = g_boff[blockIdx.x] + s[t];
    }
}

__global__ void k_fill(const int* __restrict__ ei, int E, int n) {
    int e = blockIdx.x * blockDim.x + threadIdx.x;
    if (e < E) {
        int src = clampi(ei[e], n);
        int dst = clampi(ei[E + e], n);
        int p = atomicAdd(&g_cursor[dst], 1);
        g_col[p] = src;
    }
}

// ---------------- HMMA GEMM, smem-free -----------------------------------
// A fragments loaded directly from gmem (row-major fp16/fp32 rows).
// N-split: CTA computes 128 rows x 64 cols (nh = blockIdx.x & 1).
__global__ void __launch_bounds__(256)
k_gemm_mma(const float* __restrict__ xin, int layer, int n, int src) {
    int tid = threadIdx.x;
    int wid = tid >> 5, lane = tid & 31;
    int nh = blockIdx.x & 1;
    int rb = (blockIdx.x >> 1) * 128;

    int r0 = rb + wid * 16 + (lane >> 2);   // fragment row (low)
    int r1 = r0 + 8;                        // fragment row (high)
    int rl = (r0 < n) ? r0 : (n - 1);       // clamped load rows
    int rh = (r1 < n) ? r1 : (n - 1);
    int c0 = 2 * (lane & 3);                // k offset within 8-group

    float acc[8][4];
    #pragma unroll
    for (int f = 0; f < 8; f++)
        #pragma unroll
        for (int j = 0; j < 4; j++) acc[f][j] = 0.f;

    const uint2* bf = g_bfrag + (layer * 8) * 16 * 32 + (nh * 8) * 32;

    #pragma unroll
    for (int s = 0; s < 8; s++) {
        uint32_t a0, a1, a2, a3;
        int k0 = s * 16 + c0;
        if (src == 0) {
            const float* xl = xin + (long long)rl * HDIM;
            const float* xh = xin + (long long)rh * HDIM;
            float2 f0 = *(const float2*)(xl + k0);
            float2 f1 = *(const float2*)(xh + k0);
            float2 f2 = *(const float2*)(xl + k0 + 8);
            float2 f3 = *(const float2*)(xh + k0 + 8);
            __half2 h0 = __floats2half2_rn(f0.x, f0.y);
            __half2 h1 = __floats2half2_rn(f1.x, f1.y);
            __half2 h2 = __floats2half2_rn(f2.x, f2.y);
            __half2 h3 = __floats2half2_rn(f3.x, f3.y);
            a0 = *(unsigned int*)&h0; a1 = *(unsigned int*)&h1;
            a2 = *(unsigned int*)&h2; a3 = *(unsigned int*)&h3;
        } else {
            a0 = *(const unsigned int*)(g_feat16 + (long long)rl * HDIM + k0);
            a1 = *(const unsigned int*)(g_feat16 + (long long)rh * HDIM + k0);
            a2 = *(const unsigned int*)(g_feat16 + (long long)rl * HDIM + k0 + 8);
            a3 = *(const unsigned int*)(g_feat16 + (long long)rh * HDIM + k0 + 8);
        }
        const uint2* bs = bf + s * 16 * 32 + lane;
        #pragma unroll
        for (int f = 0; f < 8; f++) {
            uint2 b = __ldg(&bs[f * 32]);
            asm volatile(
                "mma.sync.aligned.m16n8k16.row.col.f32.f16.f16.f32 "
                "{%0,%1,%2,%3}, {%4,%5,%6,%7}, {%8,%9}, {%0,%1,%2,%3};"
                : "+f"(acc[f][0]), "+f"(acc[f][1]), "+f"(acc[f][2]), "+f"(acc[f][3])
                : "r"(a0), "r"(a1), "r"(a2), "r"(a3), "r"(b.x), "r"(b.y));
        }
    }

    float di0 = (r0 < n) ? g_dinv[r0] : 0.f;
    float di1 = (r1 < n) ? g_dinv[r1] : 0.f;
    #pragma unroll
    for (int f = 0; f < 8; f++) {
        int c = nh * 64 + f * 8 + c0;
        if (r0 < n) {
            __half2 h = __floats2half2_rn(acc[f][0] * di0, acc[f][1] * di0);
            *(unsigned int*)(g_hs16 + (long long)r0 * HDIM + c) = *(unsigned int*)&h;
        }
        if (r1 < n) {
            __half2 h = __floats2half2_rn(acc[f][2] * di1, acc[f][3] * di1);
            *(unsigned int*)(g_hs16 + (long long)r1 * HDIM + c) = *(unsigned int*)&h;
        }
    }
}

// ---------------- 128-wide pull aggregation (padded CSR, no masks) ------
__global__ void __launch_bounds__(256)
k_agg128(const float* __restrict__ bias, const float* __restrict__ Wout,
         int n, int fin) {
    __shared__ float Wsm[HDIM * CDIM];
    if (fin) {
        for (int i = threadIdx.x; i < HDIM * CDIM; i += 256)
            Wsm[i] = Wout[i];
        __syncthreads();
    }
    int w = (blockIdx.x * 256 + threadIdx.x) >> 5;
    int lane = threadIdx.x & 31;
    if (w >= n) return;
    const uint2* base = (const uint2*)g_hs16;
    float4 acc;
    {
        uint2 v = base[w * 32 + lane];       // self loop
        float2 f0 = __half22float2(*(__half2*)&v.x);
        float2 f1 = __half22float2(*(__half2*)&v.y);
        acc.x = f0.x; acc.y = f0.y; acc.z = f1.x; acc.w = f1.y;
    }
    int e0 = g_rowptr[w], e1 = g_rowptr[w + 1];
    for (int e = e0; e < e1; e += 32) {
        int me = e + lane;
        int ms = (me < e1) ? g_col[me] : NNODE;
        #pragma unroll
        for (int g = 0; g < 32; g += 8) {
            if (e + g >= e1) break;          // groups of 8 always complete
            uint2 b[8];
            #pragma unroll
            for (int j = 0; j < 8; j++) {
                int s = __shfl_sync(0xffffffffu, ms, g + j);
                b[j] = base[s * 32 + lane];
            }
            #pragma unroll
            for (int j = 0; j < 8; j++) {
                float2 f0 = __half22float2(*(__half2*)&b[j].x);
                float2 f1 = __half22float2(*(__half2*)&b[j].y);
                acc.x += f0.x; acc.y += f0.y; acc.z += f1.x; acc.w += f1.y;
            }
        }
    }
    float di = g_dinv[w];
    float4 bv = ((const float4*)bias)[lane];
    float4 o;
    o.x = fmaxf(fmaf(di, acc.x, bv.x), 0.f);
    o.y = fmaxf(fmaf(di, acc.y, bv.y), 0.f);
    o.z = fmaxf(fmaf(di, acc.z, bv.z), 0.f);
    o.w = fmaxf(fmaf(di, acc.w, bv.w), 0.f);

    if (!fin) {
        __half2 h0 = __floats2half2_rn(o.x, o.y);
        __half2 h1 = __floats2half2_rn(o.z, o.w);
        uint2 st;
        st.x = *(unsigned int*)&h0;
        st.y = *(unsigned int*)&h1;
        ((uint2*)g_feat16)[w * 32 + lane] = st;
    } else {
        float oa[4] = {o.x, o.y, o.z, o.w};
        float p[CDIM];
        #pragma unroll
        for (int c = 0; c < CDIM; c++) p[c] = 0.f;
        #pragma unroll
        for (int j = 0; j < 4; j++) {
            const float* wr = &Wsm[(4 * lane + j) * CDIM];
            #pragma unroll
            for (int c = 0; c < CDIM; c++)
                p[c] = fmaf(oa[j], wr[c], p[c]);
        }
        #pragma unroll
        for (int c = 0; c < CDIM; c++) {
            #pragma unroll
            for (int off = 16; off > 0; off >>= 1)
                p[c] += __shfl_xor_sync(0xffffffffu, p[c], off);
        }
        if (lane == 0) {
            float* dst = &g_h10[w * CDIM];
            #pragma unroll
            for (int c = 0; c < CDIM; c++) dst[c] = p[c] * di;
        }
    }
}

// 10-wide aggregation fused with mean-pool (padded CSR, 8-deep batches)
__global__ void __launch_bounds__(256)
k_agg10pool(const float* __restrict__ bias, const int* __restrict__ batch,
            int n) {
    int w = (blockIdx.x * 256 + threadIdx.x) >> 5;
    int lane = threadIdx.x & 31;
    if (w >= n) return;
    float acc = (lane < CDIM) ? g_h10[w * CDIM + lane] : 0.f;
    int e0 = g_rowptr[w], e1 = g_rowptr[w + 1];
    for (int e = e0; e < e1; e += 32) {
        int me = e + lane;
        int ms = (me < e1) ? g_col[me] : NNODE;
        #pragma unroll
        for (int g = 0; g < 32; g += 8) {
            if (e + g >= e1) break;
            float v[8];
            #pragma unroll
            for (int j = 0; j < 8; j++) {
                int s = __shfl_sync(0xffffffffu, ms, g + j);
                v[j] = (lane < CDIM) ? g_h10[s * CDIM + lane] : 0.f;
            }
            #pragma unroll
            for (int j = 0; j < 8; j++) acc += v[j];
        }
    }
    if (lane < CDIM) {
        float val = fmaf(g_dinv[w], acc, bias[lane]);
        int g = clampi(batch[w], NGRAPH);
        atomicAdd(&g_sums[g * CDIM + lane], val);
    }
}

__global__ void k_logsm(float* __restrict__ out) {
    int g = blockIdx.x * blockDim.x + threadIdx.x;
    if (g >= NGRAPH) return;
    float c = fmaxf(g_cnts[g], 1.0f);
    float p[CDIM];
    float m = -1e30f;
    #pragma unroll
    for (int i = 0; i < CDIM; i++) {
        p[i] = g_sums[g * CDIM + i] / c;
        m = fmaxf(m, p[i]);
    }
    float s = 0.f;
    #pragma unroll
    for (int i = 0; i < CDIM; i++) s += expf(p[i] - m);
    float l = logf(s);
    #pragma unroll
    for (int i = 0; i < CDIM; i++) out[g * CDIM + i] = p[i] - m - l;
}

// ---------------- launch -------------------------------------------------
extern "C" void kernel_launch(void* const* d_in, const int* in_sizes, int n_in,
                              void* d_out, int out_size) {
    const float* x     = (const float*)d_in[0];
    const int*   ei    = (const int*)d_in[1];
    const int*   batch = (const int*)d_in[2];
    const float* W_in  = (const float*)d_in[3];
    const float* b_in  = (const float*)d_in[4];
    const float* W_h0  = (const float*)d_in[5];
    const float* b_h0  = (const float*)d_in[6];
    const float* W_h1  = (const float*)d_in[7];
    const float* b_h1  = (const float*)d_in[8];
    const float* W_out = (const float*)d_in[9];
    const float* b_out = (const float*)d_in[10];

    int n = in_sizes[0] / HDIM;
    int E = in_sizes[1] / 2;

    const int TPB = 256;
    int nblk_z = (EPAD + TPB - 1) / TPB;
    int nblk_e = (E + TPB - 1) / TPB;
    int nblk_n = (n + TPB - 1) / TPB;
    int nb = (n + 1023) / 1024;
    int gb = 2 * ((n + 127) / 128);
    int agg_blocks = (n * 32 + TPB - 1) / TPB;

    k_zero<<<nblk_z, TPB>>>(n);
    k_count<<<nblk_e, TPB>>>(ei, batch, E, n);
    k_dinv_prepW<<<nblk_n, TPB>>>(W_in, W_h0, W_h1, n);
    // slot 4: layer-1 GEMM (ncu-profiled position)
    k_gemm_mma<<<gb, 256>>>(x, 0, n, 0);
    // CSR build (padded)
    k_scan1<<<nb, 1024>>>(n);
    k_scan2<<<1, 128>>>(nb);
    k_scan3<<<nb, 1024>>>(n);
    k_fill<<<nblk_e, TPB>>>(ei, E, n);
    // layer-1 aggregation
    k_agg128<<<agg_blocks, TPB>>>(b_in, W_out, n, 0);
    // Layer 2
    k_gemm_mma<<<gb, 256>>>(x, 1, n, 1);
    k_agg128<<<agg_blocks, TPB>>>(b_h0, W_out, n, 0);
    // Layer 3 (+fused 128->10 projection)
    k_gemm_mma<<<gb, 256>>>(x, 2, n, 1);
    k_agg128<<<agg_blocks, TPB>>>(b_h1, W_out, n, 1);
    // Layer 4 aggregation fused with pooling
    k_agg10pool<<<agg_blocks, TPB>>>(b_out, batch, n);
    k_logsm<<<(NGRAPH + TPB - 1) / TPB, TPB>>>((float*)d_out);
}

// round 12
// speedup vs baseline: 1.0601x; 1.0601x over previous
#include <cuda_runtime.h>
#include <cuda_fp16.h>
#include <math.h>
#include <stdint.h>

#define NNODE  100000
#define EMAX   3200000
#define EPAD   4000064              // E + 8*N headroom (padded CSR)
#define HDIM   128
#define CDIM   10
#define H10P   16                   // padded h10 row (halves) = 32 B
#define NGRAPH 512

// ---------------- scratch (device globals; no allocation allowed) -------
__device__ __half g_hs16 [(NNODE + 1) * HDIM]; // +1 dummy zero row
__device__ __half g_feat16[NNODE * HDIM];
__device__ uint2  g_bfrag[3 * 8 * 16 * 32];    // W in mma B-fragment layout
__device__ __half g_h10 [(NNODE + 1) * H10P];  // fp16, sector-aligned rows
__device__ int   g_deg [NNODE];
__device__ float g_dinv[NNODE];
__device__ int   g_rowptr[NNODE + 1];
__device__ int   g_cursor[NNODE];
__device__ int   g_col [EPAD];
__device__ int   g_bsum[128];
__device__ int   g_boff[128];
__device__ float g_sums[NGRAPH * CDIM];
__device__ float g_cnts[NGRAPH];

__device__ __forceinline__ int clampi(int v, int n) {
    return (v < 0) ? 0 : ((v >= n) ? n - 1 : v);
}

__device__ __forceinline__ uint32_t smem_u32(const void* p) {
    uint32_t a;
    asm("{ .reg .u64 t; cvta.to.shared.u64 t, %1; cvt.u32.u64 %0, t; }"
        : "=r"(a) : "l"(p));
    return a;
}

// ---------------- init: zero everything + pre-fill g_col with dummy -----
__global__ void k_zero(int n) {
    int i = blockIdx.x * blockDim.x + threadIdx.x;
    if (i < EPAD) g_col[i] = NNODE;         // dummy src (zero row)
    if (i < n) g_deg[i] = 0;
    if (i < NGRAPH * CDIM) g_sums[i] = 0.0f;
    if (i < NGRAPH) g_cnts[i] = 0.0f;
    if (i < HDIM / 2) ((unsigned int*)(g_hs16 + NNODE * HDIM))[i] = 0u;
    if (i < H10P / 2) ((unsigned int*)(g_h10 + NNODE * H10P))[i] = 0u;
}

__global__ void k_count(const int* __restrict__ ei,
                        const int* __restrict__ batch, int E, int n) {
    int e = blockIdx.x * blockDim.x + threadIdx.x;
    if (e < E) atomicAdd(&g_deg[clampi(ei[E + e], n)], 1);
    if (e < n) atomicAdd(&g_cnts[clampi(batch[e], NGRAPH)], 1.0f);
}

// fused: dinv + W fragment packing
__global__ void k_dinv_prepW(const float* __restrict__ W0,
                             const float* __restrict__ W1,
                             const float* __restrict__ W2, int n) {
    int idx = blockIdx.x * blockDim.x + threadIdx.x;
    if (idx < n) g_dinv[idx] = rsqrtf((float)(g_deg[idx] + 1));
    if (idx < 3 * 8 * 16 * 32) {
        int lane = idx & 31;
        int f = (idx >> 5) & 15;
        int s = (idx >> 9) & 7;
        int l = idx >> 12;
        const float* W = (l == 0) ? W0 : (l == 1) ? W1 : W2;
        int kb = s * 16 + 2 * (lane & 3);
        int nn = f * 8 + (lane >> 2);
        __half2 h0 = __floats2half2_rn(W[kb * HDIM + nn], W[(kb + 1) * HDIM + nn]);
        __half2 h1 = __floats2half2_rn(W[(kb + 8) * HDIM + nn], W[(kb + 9) * HDIM + nn]);
        uint2 v;
        v.x = *(unsigned int*)&h0;
        v.y = *(unsigned int*)&h1;
        g_bfrag[idx] = v;
    }
}

// scans operate on PADDED degrees: pdeg = (deg+7) & ~7
__global__ void k_scan1(int n) {
    __shared__ int s[1024];
    int t = threadIdx.x;
    int i = blockIdx.x * 1024 + t;
    s[t] = (i < n) ? ((g_deg[i] + 7) & ~7) : 0;
    __syncthreads();
    for (int st = 512; st > 0; st >>= 1) {
        if (t < st) s[t] += s[t + st];
        __syncthreads();
    }
    if (t == 0) g_bsum[blockIdx.x] = s[0];
}

__global__ void k_scan2(int nb) {
    __shared__ int s[128];
    int t = threadIdx.x;
    int my = (t < nb) ? g_bsum[t] : 0;
    s[t] = my;
    __syncthreads();
    for (int st = 1; st < 128; st <<= 1) {
        int v = (t >= st) ? s[t - st] : 0;
        __syncthreads();
        s[t] += v;
        __syncthreads();
    }
    g_boff[t] = s[t] - my;
}

__global__ void k_scan3(int n) {
    __shared__ int s[1024];
    int t = threadIdx.x;
    int i = blockIdx.x * 1024 + t;
    int v0 = (i < n) ? ((g_deg[i] + 7) & ~7) : 0;
    s[t] = v0;
    __syncthreads();
    for (int st = 1; st < 1024; st <<= 1) {
        int v = (t >= st) ? s[t - st] : 0;
        __syncthreads();
        s[t] += v;
        __syncthreads();
    }
    if (i < n) {
        int excl = g_boff[blockIdx.x] + s[t] - v0;
        g_rowptr[i] = excl;
        g_cursor[i] = excl;
        if (i == n - 1) g_rowptr[n] = g_boff[blockIdx.x] + s[t];
    }
}

__global__ void k_fill(const int* __restrict__ ei, int E, int n) {
    int e = blockIdx.x * blockDim.x + threadIdx.x;
    if (e < E) {
        int src = clampi(ei[e], n);
        int dst = clampi(ei[E + e], n);
        int p = atomicAdd(&g_cursor[dst], 1);
        g_col[p] = src;
    }
}

// ---------------- HMMA GEMM (R10 smem/ldmatrix version) ------------------
// N-split: each CTA computes 128 rows x 64 cols (nh = blockIdx.x & 1).
#define APAD 136
__global__ void __launch_bounds__(256)
k_gemm_mma(const float* __restrict__ xin, int layer, int n, int src) {
    __shared__ __half As[128 * APAD];
    int tid = threadIdx.x;
    int wid = tid >> 5, lane = tid & 31;
    int nh = blockIdx.x & 1;
    int rb = (blockIdx.x >> 1) * 128;

    for (int i = tid; i < 2048; i += 256) {
        int r = i >> 4, j = i & 15;
        int gr = rb + r;
        uint4 v = make_uint4(0u, 0u, 0u, 0u);
        if (gr < n) {
            if (src == 0) {
                const float4* p = (const float4*)(xin + (long long)gr * HDIM + j * 8);
                float4 f0 = p[0], f1 = p[1];
                __half2 h0 = __floats2half2_rn(f0.x, f0.y);
                __half2 h1 = __floats2half2_rn(f0.z, f0.w);
                __half2 h2 = __floats2half2_rn(f1.x, f1.y);
                __half2 h3 = __floats2half2_rn(f1.z, f1.w);
                v.x = *(unsigned int*)&h0; v.y = *(unsigned int*)&h1;
                v.z = *(unsigned int*)&h2; v.w = *(unsigned int*)&h3;
            } else {
                v = *(const uint4*)(g_feat16 + (long long)gr * HDIM + j * 8);
            }
        }
        *(uint4*)&As[r * APAD + j * 8] = v;
    }
    __syncthreads();

    float acc[8][4];
    #pragma unroll
    for (int f = 0; f < 8; f++)
        #pragma unroll
        for (int j = 0; j < 4; j++) acc[f][j] = 0.f;

    const uint2* bf = g_bfrag + (layer * 8) * 16 * 32 + (nh * 8) * 32;
    int wr = wid * 16;
    int g = lane >> 3, rr = lane & 7;
    uint32_t a_base = smem_u32(As) +
        (uint32_t)(((wr + (g & 1) * 8 + rr) * APAD) * 2);

    #pragma unroll
    for (int s = 0; s < 8; s++) {
        uint32_t a0, a1, a2, a3;
        uint32_t addr = a_base + (uint32_t)((s * 16 + (g >> 1) * 8) * 2);
        asm volatile("ldmatrix.sync.aligned.m8n8.x4.shared.b16 {%0,%1,%2,%3}, [%4];"
                     : "=r"(a0), "=r"(a1), "=r"(a2), "=r"(a3) : "r"(addr));
        const uint2* bs = bf + s * 16 * 32 + lane;
        #pragma unroll
        for (int f = 0; f < 8; f++) {
            uint2 b = __ldg(&bs[f * 32]);
            asm volatile(
                "mma.sync.aligned.m16n8k16.row.col.f32.f16.f16.f32 "
                "{%0,%1,%2,%3}, {%4,%5,%6,%7}, {%8,%9}, {%0,%1,%2,%3};"
                : "+f"(acc[f][0]), "+f"(acc[f][1]), "+f"(acc[f][2]), "+f"(acc[f][3])
                : "r"(a0), "r"(a1), "r"(a2), "r"(a3), "r"(b.x), "r"(b.y));
        }
    }

    int r0 = rb + wr + (lane >> 2);
    int r1 = r0 + 8;
    float di0 = (r0 < n) ? g_dinv[r0] : 0.f;
    float di1 = (r1 < n) ? g_dinv[r1] : 0.f;
    #pragma unroll
    for (int f = 0; f < 8; f++) {
        int c = nh * 64 + f * 8 + 2 * (lane & 3);
        if (r0 < n) {
            __half2 h = __floats2half2_rn(acc[f][0] * di0, acc[f][1] * di0);
            *(unsigned int*)(g_hs16 + (long long)r0 * HDIM + c) = *(unsigned int*)&h;
        }
        if (r1 < n) {
            __half2 h = __floats2half2_rn(acc[f][2] * di1, acc[f][3] * di1);
            *(unsigned int*)(g_hs16 + (long long)r1 * HDIM + c) = *(unsigned int*)&h;
        }
    }
}

// ---------------- 128-wide pull aggregation (padded CSR, no masks) ------
__global__ void __launch_bounds__(256)
k_agg128(const float* __restrict__ bias, const float* __restrict__ Wout,
         int n, int fin) {
    __shared__ float Wsm[HDIM * CDIM];
    if (fin) {
        for (int i = threadIdx.x; i < HDIM * CDIM; i += 256)
            Wsm[i] = Wout[i];
        __syncthreads();
    }
    int w = (blockIdx.x * 256 + threadIdx.x) >> 5;
    int lane = threadIdx.x & 31;
    if (w >= n) return;
    const uint2* base = (const uint2*)g_hs16;
    float4 acc;
    {
        uint2 v = base[w * 32 + lane];       // self loop
        float2 f0 = __half22float2(*(__half2*)&v.x);
        float2 f1 = __half22float2(*(__half2*)&v.y);
        acc.x = f0.x; acc.y = f0.y; acc.z = f1.x; acc.w = f1.y;
    }
    int e0 = g_rowptr[w], e1 = g_rowptr[w + 1];
    for (int e = e0; e < e1; e += 32) {
        int me = e + lane;
        int ms = (me < e1) ? g_col[me] : NNODE;
        #pragma unroll
        for (int g = 0; g < 32; g += 8) {
            if (e + g >= e1) break;          // groups of 8 always complete
            uint2 b[8];
            #pragma unroll
            for (int j = 0; j < 8; j++) {
                int s = __shfl_sync(0xffffffffu, ms, g + j);
                b[j] = base[s * 32 + lane];
            }
            #pragma unroll
            for (int j = 0; j < 8; j++) {
                float2 f0 = __half22float2(*(__half2*)&b[j].x);
                float2 f1 = __half22float2(*(__half2*)&b[j].y);
                acc.x += f0.x; acc.y += f0.y; acc.z += f1.x; acc.w += f1.y;
            }
        }
    }
    float di = g_dinv[w];
    float4 bv = ((const float4*)bias)[lane];
    float4 o;
    o.x = fmaxf(fmaf(di, acc.x, bv.x), 0.f);
    o.y = fmaxf(fmaf(di, acc.y, bv.y), 0.f);
    o.z = fmaxf(fmaf(di, acc.z, bv.z), 0.f);
    o.w = fmaxf(fmaf(di, acc.w, bv.w), 0.f);

    if (!fin) {
        __half2 h0 = __floats2half2_rn(o.x, o.y);
        __half2 h1 = __floats2half2_rn(o.z, o.w);
        uint2 st;
        st.x = *(unsigned int*)&h0;
        st.y = *(unsigned int*)&h1;
        ((uint2*)g_feat16)[w * 32 + lane] = st;
    } else {
        float oa[4] = {o.x, o.y, o.z, o.w};
        float p[CDIM];
        #pragma unroll
        for (int c = 0; c < CDIM; c++) p[c] = 0.f;
        #pragma unroll
        for (int j = 0; j < 4; j++) {
            const float* wr = &Wsm[(4 * lane + j) * CDIM];
            #pragma unroll
            for (int c = 0; c < CDIM; c++)
                p[c] = fmaf(oa[j], wr[c], p[c]);
        }
        #pragma unroll
        for (int c = 0; c < CDIM; c++) {
            #pragma unroll
            for (int off = 16; off > 0; off >>= 1)
                p[c] += __shfl_xor_sync(0xffffffffu, p[c], off);
        }
        if (lane == 0) {
            // fp16 h10 row, 16 halves (32 B sector-aligned), last 6 zero
            __half* dst = &g_h10[w * H10P];
            unsigned int pk[8];
            #pragma unroll
            for (int c = 0; c < 5; c++) {
                __half2 h = __floats2half2_rn(p[2 * c] * di, p[2 * c + 1] * di);
                pk[c] = *(unsigned int*)&h;
            }
            pk[5] = 0u; pk[6] = 0u; pk[7] = 0u;
            uint4* d4 = (uint4*)dst;
            d4[0] = make_uint4(pk[0], pk[1], pk[2], pk[3]);
            d4[1] = make_uint4(pk[4], pk[5], pk[6], pk[7]);
        }
    }
}

// 10-wide aggregation fused with mean-pool (fp16 h10, padded CSR)
__global__ void __launch_bounds__(256)
k_agg10pool(const float* __restrict__ bias, const int* __restrict__ batch,
            int n) {
    int w = (blockIdx.x * 256 + threadIdx.x) >> 5;
    int lane = threadIdx.x & 31;
    if (w >= n) return;
    float acc = (lane < CDIM) ? __half2float(g_h10[w * H10P + lane]) : 0.f;
    int e0 = g_rowptr[w], e1 = g_rowptr[w + 1];
    for (int e = e0; e < e1; e += 32) {
        int me = e + lane;
        int ms = (me < e1) ? g_col[me] : NNODE;
        #pragma unroll
        for (int g = 0; g < 32; g += 8) {
            if (e + g >= e1) break;
            float v[8];
            #pragma unroll
            for (int j = 0; j < 8; j++) {
                int s = __shfl_sync(0xffffffffu, ms, g + j);
                v[j] = (lane < CDIM) ? __half2float(g_h10[s * H10P + lane]) : 0.f;
            }
            #pragma unroll
            for (int j = 0; j < 8; j++) acc += v[j];
        }
    }
    if (lane < CDIM) {
        float val = fmaf(g_dinv[w], acc, bias[lane]);
        int g = clampi(batch[w], NGRAPH);
        atomicAdd(&g_sums[g * CDIM + lane], val);
    }
}

__global__ void k_logsm(float* __restrict__ out) {
    int g = blockIdx.x * blockDim.x + threadIdx.x;
    if (g >= NGRAPH) return;
    float c = fmaxf(g_cnts[g], 1.0f);
    float p[CDIM];
    float m = -1e30f;
    #pragma unroll
    for (int i = 0; i < CDIM; i++) {
        p[i] = g_sums[g * CDIM + i] / c;
        m = fmaxf(m, p[i]);
    }
    float s = 0.f;
    #pragma unroll
    for (int i = 0; i < CDIM; i++) s += expf(p[i] - m);
    float l = logf(s);
    #pragma unroll
    for (int i = 0; i < CDIM; i++) out[g * CDIM + i] = p[i] - m - l;
}

// ---------------- launch -------------------------------------------------
extern "C" void kernel_launch(void* const* d_in, const int* in_sizes, int n_in,
                              void* d_out, int out_size) {
    const float* x     = (const float*)d_in[0];
    const int*   ei    = (const int*)d_in[1];
    const int*   batch = (const int*)d_in[2];
    const float* W_in  = (const float*)d_in[3];
    const float* b_in  = (const float*)d_in[4];
    const float* W_h0  = (const float*)d_in[5];
    const float* b_h0  = (const float*)d_in[6];
    const float* W_h1  = (const float*)d_in[7];
    const float* b_h1  = (const float*)d_in[8];
    const float* W_out = (const float*)d_in[9];
    const float* b_out = (const float*)d_in[10];

    int n = in_sizes[0] / HDIM;
    int E = in_sizes[1] / 2;

    const int TPB = 256;
    int nblk_z = (EPAD + TPB - 1) / TPB;
    int nblk_e = (E + TPB - 1) / TPB;
    int nblk_n = (n + TPB - 1) / TPB;
    int nb = (n + 1023) / 1024;
    int gb = 2 * ((n + 127) / 128);
    int agg_blocks = (n * 32 + TPB - 1) / TPB;

    k_zero<<<nblk_z, TPB>>>(n);
    k_count<<<nblk_e, TPB>>>(ei, batch, E, n);
    k_dinv_prepW<<<nblk_n, TPB>>>(W_in, W_h0, W_h1, n);
    // slot 4: layer-1 GEMM (ncu-profiled position)
    k_gemm_mma<<<gb, 256>>>(x, 0, n, 0);
    // CSR build (padded)
    k_scan1<<<nb, 1024>>>(n);
    k_scan2<<<1, 128>>>(nb);
    k_scan3<<<nb, 1024>>>(n);
    k_fill<<<nblk_e, TPB>>>(ei, E, n);
    // layer-1 aggregation
    k_agg128<<<agg_blocks, TPB>>>(b_in, W_out, n, 0);
    // Layer 2
    k_gemm_mma<<<gb, 256>>>(x, 1, n, 1);
    k_agg128<<<agg_blocks, TPB>>>(b_h0, W_out, n, 0);
    // Layer 3 (+fused 128->10 projection, fp16 output)
    k_gemm_mma<<<gb, 256>>>(x, 2, n, 1);
    k_agg128<<<agg_blocks, TPB>>>(b_h1, W_out, n, 1);
    // Layer 4 aggregation fused with pooling
    k_agg10pool<<<agg_blocks, TPB>>>(b_out, batch, n);
    k_logsm<<<(NGRAPH + TPB - 1) / TPB, TPB>>>((float*)d_out);
}

// round 13
// speedup vs baseline: 1.0857x; 1.0242x over previous
#include <cuda_runtime.h>
#include <cuda_fp16.h>
#include <math.h>
#include <stdint.h>

#define NNODE  100000
#define EMAX   3200000
#define EPAD   4000064              // E + 8*N headroom (padded CSR)
#define HDIM   128
#define CDIM   10
#define H10P   16                   // padded h10 row (halves) = 32 B
#define NGRAPH 512

// ---------------- scratch (device globals; no allocation allowed) -------
__device__ __half g_hs16 [(NNODE + 1) * HDIM]; // +1 dummy zero row
__device__ __half g_feat16[NNODE * HDIM];
__device__ uint2  g_bfrag[3 * 8 * 16 * 32];    // W in mma B-fragment layout
__device__ __half g_h10 [(NNODE + 1) * H10P];  // fp16, sector-aligned rows
__device__ int   g_deg [NNODE];
__device__ float g_dinv[NNODE];
__device__ int   g_rowptr[NNODE + 1];
__device__ int   g_cursor[NNODE];
__device__ int   g_col [EPAD];
__device__ int   g_bsum[128];
__device__ int   g_boff[128];
__device__ float g_sums[NGRAPH * CDIM];
__device__ float g_cnts[NGRAPH];

__device__ __forceinline__ int clampi(int v, int n) {
    return (v < 0) ? 0 : ((v >= n) ? n - 1 : v);
}

__device__ __forceinline__ uint32_t smem_u32(const void* p) {
    uint32_t a;
    asm("{ .reg .u64 t; cvta.to.shared.u64 t, %1; cvt.u32.u64 %0, t; }"
        : "=r"(a) : "l"(p));
    return a;
}

// ---------------- init ---------------------------------------------------
__global__ void k_zero(int n) {
    int i = blockIdx.x * blockDim.x + threadIdx.x;
    if (i < n) g_deg[i] = 0;
    if (i < NGRAPH * CDIM) g_sums[i] = 0.0f;
    if (i < NGRAPH) g_cnts[i] = 0.0f;
    if (i < HDIM / 2) ((unsigned int*)(g_hs16 + NNODE * HDIM))[i] = 0u;
    if (i < H10P / 2) ((unsigned int*)(g_h10 + NNODE * H10P))[i] = 0u;
}

__global__ void k_count(const int* __restrict__ ei,
                        const int* __restrict__ batch, int E, int n) {
    int e = blockIdx.x * blockDim.x + threadIdx.x;
    if (e < E) atomicAdd(&g_deg[clampi(ei[E + e], n)], 1);
    if (e < n) atomicAdd(&g_cnts[clampi(batch[e], NGRAPH)], 1.0f);
}

// fused: dinv + W fragment packing
__global__ void k_dinv_prepW(const float* __restrict__ W0,
                             const float* __restrict__ W1,
                             const float* __restrict__ W2, int n) {
    int idx = blockIdx.x * blockDim.x + threadIdx.x;
    if (idx < n) g_dinv[idx] = rsqrtf((float)(g_deg[idx] + 1));
    if (idx < 3 * 8 * 16 * 32) {
        int lane = idx & 31;
        int f = (idx >> 5) & 15;
        int s = (idx >> 9) & 7;
        int l = idx >> 12;
        const float* W = (l == 0) ? W0 : (l == 1) ? W1 : W2;
        int kb = s * 16 + 2 * (lane & 3);
        int nn = f * 8 + (lane >> 2);
        __half2 h0 = __floats2half2_rn(W[kb * HDIM + nn], W[(kb + 1) * HDIM + nn]);
        __half2 h1 = __floats2half2_rn(W[(kb + 8) * HDIM + nn], W[(kb + 9) * HDIM + nn]);
        uint2 v;
        v.x = *(unsigned int*)&h0;
        v.y = *(unsigned int*)&h1;
        g_bfrag[idx] = v;
    }
}

// scans operate on PADDED degrees: pdeg = (deg+7) & ~7
__global__ void k_scan1(int n) {
    __shared__ int s[1024];
    int t = threadIdx.x;
    int i = blockIdx.x * 1024 + t;
    s[t] = (i < n) ? ((g_deg[i] + 7) & ~7) : 0;
    __syncthreads();
    for (int st = 512; st > 0; st >>= 1) {
        if (t < st) s[t] += s[t + st];
        __syncthreads();
    }
    if (t == 0) g_bsum[blockIdx.x] = s[0];
}

__global__ void k_scan2(int nb) {
    __shared__ int s[128];
    int t = threadIdx.x;
    int my = (t < nb) ? g_bsum[t] : 0;
    s[t] = my;
    __syncthreads();
    for (int st = 1; st < 128; st <<= 1) {
        int v = (t >= st) ? s[t - st] : 0;
        __syncthreads();
        s[t] += v;
        __syncthreads();
    }
    g_boff[t] = s[t] - my;
}

__global__ void k_scan3(int n) {
    __shared__ int s[1024];
    int t = threadIdx.x;
    int i = blockIdx.x * 1024 + t;
    int v0 = (i < n) ? ((g_deg[i] + 7) & ~7) : 0;
    s[t] = v0;
    __syncthreads();
    for (int st = 1; st < 1024; st <<= 1) {
        int v = (t >= st) ? s[t - st] : 0;
        __syncthreads();
        s[t] += v;
        __syncthreads();
    }
    if (i < n) {
        int excl = g_boff[blockIdx.x] + s[t] - v0;
        g_rowptr[i] = excl;
        g_cursor[i] = excl;
        if (i == n - 1) g_rowptr[n] = g_boff[blockIdx.x] + s[t];
    }
}

__global__ void k_fill(const int* __restrict__ ei, int E, int n) {
    int e = blockIdx.x * blockDim.x + threadIdx.x;
    if (e < E) {
        int src = clampi(ei[e], n);
        int dst = clampi(ei[E + e], n);
        int p = atomicAdd(&g_cursor[dst], 1);
        g_col[p] = src;
    }
}

// fill padding slots (<=7 per node) with dummy index
__global__ void k_padfill(int n) {
    int i = blockIdx.x * blockDim.x + threadIdx.x;
    if (i >= n) return;
    int p0 = g_rowptr[i] + g_deg[i];
    int p1 = g_rowptr[i + 1];
    for (int p = p0; p < p1; p++) g_col[p] = NNODE;
}

// ---------------- HMMA GEMM (smem/ldmatrix, N-split) ---------------------
#define APAD 136
__global__ void __launch_bounds__(256)
k_gemm_mma(const float* __restrict__ xin, int layer, int n, int src) {
    __shared__ __half As[128 * APAD];
    int tid = threadIdx.x;
    int wid = tid >> 5, lane = tid & 31;
    int nh = blockIdx.x & 1;
    int rb = (blockIdx.x >> 1) * 128;

    for (int i = tid; i < 2048; i += 256) {
        int r = i >> 4, j = i & 15;
        int gr = rb + r;
        uint4 v = make_uint4(0u, 0u, 0u, 0u);
        if (gr < n) {
            if (src == 0) {
                const float4* p = (const float4*)(xin + (long long)gr * HDIM + j * 8);
                float4 f0 = p[0], f1 = p[1];
                __half2 h0 = __floats2half2_rn(f0.x, f0.y);
                __half2 h1 = __floats2half2_rn(f0.z, f0.w);
                __half2 h2 = __floats2half2_rn(f1.x, f1.y);
                __half2 h3 = __floats2half2_rn(f1.z, f1.w);
                v.x = *(unsigned int*)&h0; v.y = *(unsigned int*)&h1;
                v.z = *(unsigned int*)&h2; v.w = *(unsigned int*)&h3;
            } else {
                v = *(const uint4*)(g_feat16 + (long long)gr * HDIM + j * 8);
            }
        }
        *(uint4*)&As[r * APAD + j * 8] = v;
    }
    __syncthreads();

    float acc[8][4];
    #pragma unroll
    for (int f = 0; f < 8; f++)
        #pragma unroll
        for (int j = 0; j < 4; j++) acc[f][j] = 0.f;

    const uint2* bf = g_bfrag + (layer * 8) * 16 * 32 + (nh * 8) * 32;
    int wr = wid * 16;
    int g = lane >> 3, rr = lane & 7;
    uint32_t a_base = smem_u32(As) +
        (uint32_t)(((wr + (g & 1) * 8 + rr) * APAD) * 2);

    #pragma unroll
    for (int s = 0; s < 8; s++) {
        uint32_t a0, a1, a2, a3;
        uint32_t addr = a_base + (uint32_t)((s * 16 + (g >> 1) * 8) * 2);
        asm volatile("ldmatrix.sync.aligned.m8n8.x4.shared.b16 {%0,%1,%2,%3}, [%4];"
                     : "=r"(a0), "=r"(a1), "=r"(a2), "=r"(a3) : "r"(addr));
        const uint2* bs = bf + s * 16 * 32 + lane;
        #pragma unroll
        for (int f = 0; f < 8; f++) {
            uint2 b = __ldg(&bs[f * 32]);
            asm volatile(
                "mma.sync.aligned.m16n8k16.row.col.f32.f16.f16.f32 "
                "{%0,%1,%2,%3}, {%4,%5,%6,%7}, {%8,%9}, {%0,%1,%2,%3};"
                : "+f"(acc[f][0]), "+f"(acc[f][1]), "+f"(acc[f][2]), "+f"(acc[f][3])
                : "r"(a0), "r"(a1), "r"(a2), "r"(a3), "r"(b.x), "r"(b.y));
        }
    }

    int r0 = rb + wr + (lane >> 2);
    int r1 = r0 + 8;
    float di0 = (r0 < n) ? g_dinv[r0] : 0.f;
    float di1 = (r1 < n) ? g_dinv[r1] : 0.f;
    #pragma unroll
    for (int f = 0; f < 8; f++) {
        int c = nh * 64 + f * 8 + 2 * (lane & 3);
        if (r0 < n) {
            __half2 h = __floats2half2_rn(acc[f][0] * di0, acc[f][1] * di0);
            *(unsigned int*)(g_hs16 + (long long)r0 * HDIM + c) = *(unsigned int*)&h;
        }
        if (r1 < n) {
            __half2 h = __floats2half2_rn(acc[f][2] * di1, acc[f][3] * di1);
            *(unsigned int*)(g_hs16 + (long long)r1 * HDIM + c) = *(unsigned int*)&h;
        }
    }
}

// ---------------- 128-wide pull aggregation (padded CSR, no masks) ------
__global__ void __launch_bounds__(256)
k_agg128(const float* __restrict__ bias, const float* __restrict__ Wout,
         int n, int fin) {
    __shared__ float Wsm[HDIM * CDIM];
    if (fin) {
        for (int i = threadIdx.x; i < HDIM * CDIM; i += 256)
            Wsm[i] = Wout[i];
        __syncthreads();
    }
    int w = (blockIdx.x * 256 + threadIdx.x) >> 5;
    int lane = threadIdx.x & 31;
    if (w >= n) return;
    const uint2* base = (const uint2*)g_hs16;
    float4 acc;
    {
        uint2 v = base[w * 32 + lane];       // self loop
        float2 f0 = __half22float2(*(__half2*)&v.x);
        float2 f1 = __half22float2(*(__half2*)&v.y);
        acc.x = f0.x; acc.y = f0.y; acc.z = f1.x; acc.w = f1.y;
    }
    int e0 = g_rowptr[w], e1 = g_rowptr[w + 1];
    for (int e = e0; e < e1; e += 32) {
        int me = e + lane;
        int ms = (me < e1) ? g_col[me] : NNODE;
        #pragma unroll
        for (int g = 0; g < 32; g += 8) {
            if (e + g >= e1) break;          // groups of 8 always complete
            uint2 b[8];
            #pragma unroll
            for (int j = 0; j < 8; j++) {
                int s = __shfl_sync(0xffffffffu, ms, g + j);
                b[j] = base[s * 32 + lane];
            }
            #pragma unroll
            for (int j = 0; j < 8; j++) {
                float2 f0 = __half22float2(*(__half2*)&b[j].x);
                float2 f1 = __half22float2(*(__half2*)&b[j].y);
                acc.x += f0.x; acc.y += f0.y; acc.z += f1.x; acc.w += f1.y;
            }
        }
    }
    float di = g_dinv[w];
    float4 bv = ((const float4*)bias)[lane];
    float4 o;
    o.x = fmaxf(fmaf(di, acc.x, bv.x), 0.f);
    o.y = fmaxf(fmaf(di, acc.y, bv.y), 0.f);
    o.z = fmaxf(fmaf(di, acc.z, bv.z), 0.f);
    o.w = fmaxf(fmaf(di, acc.w, bv.w), 0.f);

    if (!fin) {
        __half2 h0 = __floats2half2_rn(o.x, o.y);
        __half2 h1 = __floats2half2_rn(o.z, o.w);
        uint2 st;
        st.x = *(unsigned int*)&h0;
        st.y = *(unsigned int*)&h1;
        ((uint2*)g_feat16)[w * 32 + lane] = st;
    } else {
        float oa[4] = {o.x, o.y, o.z, o.w};
        float p[CDIM];
        #pragma unroll
        for (int c = 0; c < CDIM; c++) p[c] = 0.f;
        #pragma unroll
        for (int j = 0; j < 4; j++) {
            const float* wr = &Wsm[(4 * lane + j) * CDIM];
            #pragma unroll
            for (int c = 0; c < CDIM; c++)
                p[c] = fmaf(oa[j], wr[c], p[c]);
        }
        #pragma unroll
        for (int c = 0; c < CDIM; c++) {
            #pragma unroll
            for (int off = 16; off > 0; off >>= 1)
                p[c] += __shfl_xor_sync(0xffffffffu, p[c], off);
        }
        if (lane == 0) {
            __half* dst = &g_h10[w * H10P];
            unsigned int pk[8];
            #pragma unroll
            for (int c = 0; c < 5; c++) {
                __half2 h = __floats2half2_rn(p[2 * c] * di, p[2 * c + 1] * di);
                pk[c] = *(unsigned int*)&h;
            }
            pk[5] = 0u; pk[6] = 0u; pk[7] = 0u;
            uint4* d4 = (uint4*)dst;
            d4[0] = make_uint4(pk[0], pk[1], pk[2], pk[3]);
            d4[1] = make_uint4(pk[4], pk[5], pk[6], pk[7]);
        }
    }
}

// 10-wide aggregation fused with mean-pool (fp16 h10, padded CSR)
__global__ void __launch_bounds__(256)
k_agg10pool(const float* __restrict__ bias, const int* __restrict__ batch,
            int n) {
    int w = (blockIdx.x * 256 + threadIdx.x) >> 5;
    int lane = threadIdx.x & 31;
    if (w >= n) return;
    float acc = (lane < CDIM) ? __half2float(g_h10[w * H10P + lane]) : 0.f;
    int e0 = g_rowptr[w], e1 = g_rowptr[w + 1];
    for (int e = e0; e < e1; e += 32) {
        int me = e + lane;
        int ms = (me < e1) ? g_col[me] : NNODE;
        #pragma unroll
        for (int g = 0; g < 32; g += 8) {
            if (e + g >= e1) break;
            float v[8];
            #pragma unroll
            for (int j = 0; j < 8; j++) {
                int s = __shfl_sync(0xffffffffu, ms, g + j);
                v[j] = (lane < CDIM) ? __half2float(g_h10[s * H10P + lane]) : 0.f;
            }
            #pragma unroll
            for (int j = 0; j < 8; j++) acc += v[j];
        }
    }
    if (lane < CDIM) {
        float val = fmaf(g_dinv[w], acc, bias[lane]);
        int g = clampi(batch[w], NGRAPH);
        atomicAdd(&g_sums[g * CDIM + lane], val);
    }
}

__global__ void k_logsm(float* __restrict__ out) {
    int g = blockIdx.x * blockDim.x + threadIdx.x;
    if (g >= NGRAPH) return;
    float c = fmaxf(g_cnts[g], 1.0f);
    float p[CDIM];
    float m = -1e30f;
    #pragma unroll
    for (int i = 0; i < CDIM; i++) {
        p[i] = g_sums[g * CDIM + i] / c;
        m = fmaxf(m, p[i]);
    }
    float s = 0.f;
    #pragma unroll
    for (int i = 0; i < CDIM; i++) s += expf(p[i] - m);
    float l = logf(s);
    #pragma unroll
    for (int i = 0; i < CDIM; i++) out[g * CDIM + i] = p[i] - m - l;
}

// ---------------- launch -------------------------------------------------
extern "C" void kernel_launch(void* const* d_in, const int* in_sizes, int n_in,
                              void* d_out, int out_size) {
    const float* x     = (const float*)d_in[0];
    const int*   ei    = (const int*)d_in[1];
    const int*   batch = (const int*)d_in[2];
    const float* W_in  = (const float*)d_in[3];
    const float* b_in  = (const float*)d_in[4];
    const float* W_h0  = (const float*)d_in[5];
    const float* b_h0  = (const float*)d_in[6];
    const float* W_h1  = (const float*)d_in[7];
    const float* b_h1  = (const float*)d_in[8];
    const float* W_out = (const float*)d_in[9];
    const float* b_out = (const float*)d_in[10];

    int n = in_sizes[0] / HDIM;
    int E = in_sizes[1] / 2;

    // lazy one-time stream/event creation (first call is NOT captured)
    static cudaStream_t s1 = nullptr;
    static cudaEvent_t evFork = nullptr, evJoin = nullptr;
    if (s1 == nullptr) {
        cudaStreamCreateWithFlags(&s1, cudaStreamNonBlocking);
        cudaEventCreateWithFlags(&evFork, cudaEventDisableTiming);
        cudaEventCreateWithFlags(&evJoin, cudaEventDisableTiming);
    }

    const int TPB = 256;
    int nblk_e = (E + TPB - 1) / TPB;
    int nblk_n = (n + TPB - 1) / TPB;
    int nb = (n + 1023) / 1024;
    int gb = 2 * ((n + 127) / 128);
    int agg_blocks = (n * 32 + TPB - 1) / TPB;

    k_zero<<<nblk_n, TPB>>>(n);
    k_count<<<nblk_e, TPB>>>(ei, batch, E, n);
    k_dinv_prepW<<<nblk_n, TPB>>>(W_in, W_h0, W_h1, n);

    // fork: CSR build on s1, GEMM L1 on main stream
    cudaEventRecord(evFork, 0);
    cudaStreamWaitEvent(s1, evFork, 0);
    k_scan1<<<nb, 1024, 0, s1>>>(n);
    k_scan2<<<1, 128, 0, s1>>>(nb);
    k_scan3<<<nb, 1024, 0, s1>>>(n);
    k_fill<<<nblk_e, TPB, 0, s1>>>(ei, E, n);
    k_padfill<<<nblk_n, TPB, 0, s1>>>(n);
    cudaEventRecord(evJoin, s1);

    k_gemm_mma<<<gb, 256>>>(x, 0, n, 0);      // layer-1 GEMM overlaps CSR

    // join: aggregation needs both GEMM output and CSR
    cudaStreamWaitEvent(0, evJoin, 0);
    k_agg128<<<agg_blocks, TPB>>>(b_in, W_out, n, 0);
    // Layer 2
    k_gemm_mma<<<gb, 256>>>(x, 1, n, 1);
    k_agg128<<<agg_blocks, TPB>>>(b_h0, W_out, n, 0);
    // Layer 3 (+fused 128->10 projection, fp16 output)
    k_gemm_mma<<<gb, 256>>>(x, 2, n, 1);
    k_agg128<<<agg_blocks, TPB>>>(b_h1, W_out, n, 1);
    // Layer 4 aggregation fused with pooling
    k_agg10pool<<<agg_blocks, TPB>>>(b_out, batch, n);
    k_logsm<<<(NGRAPH + TPB - 1) / TPB, TPB>>>((float*)d_out);
}